// round 14
// baseline (speedup 1.0000x reference)
#include <cuda_runtime.h>
#include <cuda_bf16.h>
#include <math.h>
#include <stdint.h>

#define BATCH 128
#define DD 256
#define HW 784
#define KXC 832
#define ITERN 7
#define ROPH 1.05
#define MAT (BATCH * DD * DD)
#define TRIL 32896
#define FC_SPLITS 16
#define FC_KSPAN 2080

// CTA tile 128(M) x 64(N); stage = Ah,Al (128x80B) + Bh,Bl (64x80B)
#define STAGE_BYTES 30720
#define MM_SMEM (2 * STAGE_BYTES)

typedef __nv_bfloat16 bf;

// ---------------- scratch ----------------
__device__ bf g_xch[BATCH * DD * KXC], g_xcl[BATCH * DD * KXC];
__device__ bf g_ypreh[MAT], g_yprel[MAT];
__device__ bf g_zy0h[MAT], g_zy0l[MAT];
__device__ bf g_yh[MAT], g_yl[MAT], g_yht[MAT], g_ylt[MAT];
__device__ bf g_zyh[MAT], g_zyl[MAT], g_zyht[MAT], g_zylt[MAT];
__device__ bf g_zah[MAT], g_zal[MAT], g_zaht[MAT], g_zalt[MAT];
__device__ bf g_zbh[MAT], g_zbl[MAT], g_zbht[MAT], g_zblt[MAT];
__device__ bf g_feath[BATCH * TRIL], g_featl[BATCH * TRIL];
__device__ bf g_fcwh[200 * TRIL], g_fcwl[200 * TRIL];
__device__ float g_Ya[MAT], g_Yb[MAT], g_L1[MAT], g_L2[MAT];
__device__ float g_mean[BATCH * DD], g_attv[BATCH * DD], g_tr[BATCH];
__device__ float g_fcp[FC_SPLITS * BATCH * 256];

#define DEVINL __device__ __forceinline__
DEVINL uint32_t s2u(const void* p) {
    uint32_t a;
    asm("{ .reg .u64 t; cvta.to.shared.u64 t, %1; cvt.u32.u64 %0, t; }" : "=r"(a) : "l"(p));
    return a;
}
DEVINL void ldmA(uint32_t* a, uint32_t addr) {
    asm volatile("ldmatrix.sync.aligned.m8n8.x4.shared.b16 {%0,%1,%2,%3}, [%4];"
                 : "=r"(a[0]), "=r"(a[1]), "=r"(a[2]), "=r"(a[3]) : "r"(addr));
}
DEVINL void ldmB(uint32_t* b, uint32_t addr) {
    asm volatile("ldmatrix.sync.aligned.m8n8.x2.shared.b16 {%0,%1}, [%2];"
                 : "=r"(b[0]), "=r"(b[1]) : "r"(addr));
}
DEVINL void mma16816(float* c, const uint32_t* a, const uint32_t* b2) {
    asm volatile(
        "mma.sync.aligned.m16n8k16.row.col.f32.bf16.bf16.f32 "
        "{%0,%1,%2,%3}, {%4,%5,%6,%7}, {%8,%9}, {%0,%1,%2,%3};"
        : "+f"(c[0]), "+f"(c[1]), "+f"(c[2]), "+f"(c[3])
        : "r"(a[0]), "r"(a[1]), "r"(a[2]), "r"(a[3]), "r"(b2[0]), "r"(b2[1]));
}
DEVINL void cpa16(uint32_t dst, const void* src, int pred) {
    asm volatile("cp.async.cg.shared.global [%0], [%1], 16, %2;"
                 :: "r"(dst), "l"(src), "r"(pred ? 16 : 0) : "memory");
}
#define CPA_COMMIT() asm volatile("cp.async.commit_group;" ::: "memory")
#define CPA_WAIT(n)  asm volatile("cp.async.wait_group %0;" :: "n"(n) : "memory")

DEVINL bf bhi(float v) { return __float2bfloat16(v); }
DEVINL bf blo(float v, bf h) { return __float2bfloat16(v - __bfloat162float(h)); }

// ---------------- split-bf16 HMMA GEMM body (CTA 128x64, 2-stage) ---------
// C[m,n] = alpha * sum_k (Ah+Al)[m,k]*(Bh+Bl)[n,k] + diag*(m==n)
// 8 warps: warpM = wid>>1 (4), warpN = wid&1 (2); warp tile 32x32.
// epi 0: fp32 out; epi 1: bf16 hi/lo planes + transposed hi/lo planes.
DEVINL void mm_body(
    const bf* __restrict__ Ah, const bf* __restrict__ Al, int lda,
    const bf* __restrict__ Bh, const bf* __restrict__ Bl, int ldb, int nbValid,
    float* __restrict__ cf, bf* __restrict__ ch, bf* __restrict__ cl,
    bf* __restrict__ chT, bf* __restrict__ clT,
    int ldc, int nlimit, int k0, int k1, float alpha, float diag,
    int rowBase, int colBase, int epi, char* smem) {
    int tid = threadIdx.x;
    int lane = tid & 31, wid = tid >> 5;
    int warpM = wid >> 1, warpN = wid & 1;

    float acc[2][4][4];
#pragma unroll
    for (int a = 0; a < 2; a++)
#pragma unroll
        for (int b = 0; b < 4; b++)
#pragma unroll
            for (int c = 0; c < 4; c++) acc[a][b][c] = 0.f;

    uint32_t smemB = s2u(smem);
    int nsteps = (k1 - k0) >> 5;
    const bf* planes[4] = { Ah, Al, Bh, Bl };
    const int toff[4] = { 0, 10240, 20480, 25600 };

#define STAGE_LOAD(stg, kt)                                                   \
    do {                                                                      \
        uint32_t base = smemB + (stg) * STAGE_BYTES;                          \
        _Pragma("unroll")                                                     \
        for (int p = 0; p < 6; p++) {                                         \
            int idx = tid + p * 256;                                          \
            int tile, r;                                                      \
            if (idx < 1024) { tile = idx >> 9; r = (idx >> 2) & 127; }        \
            else { int j = idx - 1024; tile = 2 + (j >> 8); r = (j >> 2) & 63; } \
            int s = idx & 3;                                                  \
            int pred = 1;                                                     \
            long grow_;                                                       \
            int ld_;                                                          \
            if (tile < 2) { grow_ = rowBase + r; ld_ = lda; }                 \
            else { grow_ = colBase + r; ld_ = ldb; pred = (colBase + r < nbValid); } \
            const bf* srcp = planes[tile] + grow_ * ld_ + (kt) + s * 8;       \
            cpa16(base + toff[tile] + r * 80 + s * 16, srcp, pred);           \
        }                                                                     \
        CPA_COMMIT();                                                         \
    } while (0)

    STAGE_LOAD(0, k0);

    for (int i = 0; i < nsteps; i++) {
        int stg = i & 1;
        if (i + 1 < nsteps) {
            STAGE_LOAD(stg ^ 1, k0 + (i + 1) * 32);
            CPA_WAIT(1);
        } else {
            CPA_WAIT(0);
        }
        __syncthreads();
        uint32_t sbA  = smemB + stg * STAGE_BYTES;
        uint32_t sbAl = sbA + 10240;
        uint32_t sbBh = sbA + 20480;
        uint32_t sbBl = sbA + 25600;
#pragma unroll
        for (int kk = 0; kk < 2; kk++) {
            uint32_t afh[2][4], afl[2][4], bfh[4][2], bfl[4][2];
#pragma unroll
            for (int mi = 0; mi < 2; mi++) {
                int r = warpM * 32 + mi * 16 + (lane & 15);
                ldmA(afh[mi], sbA + r * 80 + kk * 32 + ((lane >> 4) * 16));
            }
#pragma unroll
            for (int ni = 0; ni < 4; ni++) {
                int r = warpN * 32 + ni * 8 + (lane & 7);
                ldmB(bfh[ni], sbBh + r * 80 + kk * 32 + (((lane >> 3) & 1) * 16));
            }
#pragma unroll
            for (int mi = 0; mi < 2; mi++)
#pragma unroll
                for (int ni = 0; ni < 4; ni++) mma16816(acc[mi][ni], afh[mi], bfh[ni]);
#pragma unroll
            for (int ni = 0; ni < 4; ni++) {
                int r = warpN * 32 + ni * 8 + (lane & 7);
                ldmB(bfl[ni], sbBl + r * 80 + kk * 32 + (((lane >> 3) & 1) * 16));
            }
#pragma unroll
            for (int mi = 0; mi < 2; mi++)
#pragma unroll
                for (int ni = 0; ni < 4; ni++) mma16816(acc[mi][ni], afh[mi], bfl[ni]);
#pragma unroll
            for (int mi = 0; mi < 2; mi++) {
                int r = warpM * 32 + mi * 16 + (lane & 15);
                ldmA(afl[mi], sbAl + r * 80 + kk * 32 + ((lane >> 4) * 16));
            }
#pragma unroll
            for (int mi = 0; mi < 2; mi++)
#pragma unroll
                for (int ni = 0; ni < 4; ni++) mma16816(acc[mi][ni], afl[mi], bfh[ni]);
        }
        __syncthreads();
    }
#undef STAGE_LOAD

    int g = lane >> 2, t4 = lane & 3;
    if (epi == 0) {
#pragma unroll
        for (int mi = 0; mi < 2; mi++)
#pragma unroll
            for (int ni = 0; ni < 4; ni++) {
                float* c = acc[mi][ni];
                int col = colBase + warpN * 32 + ni * 8 + t4 * 2;
                if (col >= nlimit) continue;
#pragma unroll
                for (int h = 0; h < 2; h++) {
                    int row = rowBase + warpM * 32 + mi * 16 + g + h * 8;
                    float v0 = alpha * c[h * 2] + ((row == col) ? diag : 0.f);
                    float v1 = alpha * c[h * 2 + 1] + ((row == col + 1) ? diag : 0.f);
                    *(float2*)(cf + (long)row * ldc + col) = make_float2(v0, v1);
                }
            }
    } else {
        bf* Tb = (bf*)smem;   // 64 cols x 136 stride (rows 0..127)
#pragma unroll
        for (int pass = 0; pass < 2; pass++) {
#pragma unroll
            for (int mi = 0; mi < 2; mi++)
#pragma unroll
                for (int ni = 0; ni < 4; ni++) {
                    float* c = acc[mi][ni];
                    int cl0 = warpN * 32 + ni * 8 + t4 * 2;
#pragma unroll
                    for (int h = 0; h < 2; h++) {
                        int rl0 = warpM * 32 + mi * 16 + g + h * 8;
                        int rg = rowBase + rl0, cg = colBase + cl0;
                        float v0 = alpha * c[h * 2] + ((rg == cg) ? diag : 0.f);
                        float v1 = alpha * c[h * 2 + 1] + ((rg == cg + 1) ? diag : 0.f);
                        bf h0 = bhi(v0), h1 = bhi(v1);
                        bf o0 = h0, o1 = h1;
                        if (pass == 1) { o0 = blo(v0, h0); o1 = blo(v1, h1); }
                        __nv_bfloat162 pr;
                        pr.x = o0; pr.y = o1;
                        bf* dst = (pass == 0) ? ch : cl;
                        *(__nv_bfloat162*)(dst + (long)rg * ldc + cg) = pr;
                        Tb[cl0 * 136 + rl0] = o0;
                        Tb[(cl0 + 1) * 136 + rl0] = o1;
                    }
                }
            __syncthreads();
            bf* dT = (pass == 0) ? chT : clT;
#pragma unroll
            for (int q = 0; q < 4; q++) {
                int idx = tid + q * 256;      // 64 cols x 16 segs
                int tc = idx >> 4, seg = idx & 15;
                uint4 v = *(uint4*)((char*)Tb + tc * 272 + seg * 16);
                *(uint4*)(dT + (long)(colBase + tc) * ldc + rowBase + seg * 8) = v;
            }
            __syncthreads();
        }
    }
}

// generic wrapper: kspan==0 batched over blockIdx.z; kspan>0 split-K (fp32 out)
__global__ __launch_bounds__(256, 3) void mm_k(
    const bf* __restrict__ Agh, const bf* __restrict__ Agl, long aStr, int lda,
    const bf* __restrict__ Bgh, const bf* __restrict__ Bgl, long bStr, int ldb, int nbValid,
    float* __restrict__ Cf, bf* __restrict__ Ch, bf* __restrict__ Cl,
    bf* __restrict__ ChT, bf* __restrict__ ClT,
    long cStr, int ldc, int nlimit, int K, int kspan, float alpha, float diag, int epi) {
    extern __shared__ __align__(16) char smem[];
    int z = blockIdx.z;
    const bf *Ah = Agh, *Al = Agl, *Bh = Bgh, *Bl = Bgl;
    int k0 = 0, k1 = K;
    float* cf = 0;
    bf *ch = 0, *cl = 0, *chT = 0, *clT = 0;
    if (kspan) {
        k0 = z * kspan;
        k1 = min(K, k0 + kspan);
        cf = Cf + (long)z * cStr;
    } else {
        Ah += (long)z * aStr; Al += (long)z * aStr;
        Bh += (long)z * bStr; Bl += (long)z * bStr;
        if (epi == 0) cf = Cf + (long)z * cStr;
        else {
            ch = Ch + (long)z * cStr; cl = Cl + (long)z * cStr;
            chT = ChT + (long)z * cStr; clT = ClT + (long)z * cStr;
        }
    }
    mm_body(Ah, Al, lda, Bh, Bl, ldb, nbValid, cf, ch, cl, chT, clT,
            ldc, nlimit, k0, k1, alpha, diag,
            blockIdx.y * 128, blockIdx.x * 64, epi, smem);
}

// fused Ynew + Znew: z<BATCH -> Y = Yh/Yl @ ZYt (fp32); z>=BATCH -> Znew planes
__global__ __launch_bounds__(256, 3) void mmYZ_k(
    const bf* __restrict__ yh, const bf* __restrict__ yl,
    const bf* __restrict__ zyht, const bf* __restrict__ zylt, float* __restrict__ Yout,
    const bf* __restrict__ zyh, const bf* __restrict__ zyl,
    const bf* __restrict__ zcht, const bf* __restrict__ zclt,
    bf* __restrict__ oh, bf* __restrict__ ol,
    bf* __restrict__ oht, bf* __restrict__ olt) {
    extern __shared__ __align__(16) char smem[];
    int z = blockIdx.z;
    if (z < BATCH) {
        long off = (long)z * 65536;
        mm_body(yh + off, yl + off, 256, zyht + off, zylt + off, 256, 256,
                Yout + off, 0, 0, 0, 0, 256, 256, 0, 256, 1.f, 0.f,
                blockIdx.y * 128, blockIdx.x * 64, 0, smem);
    } else {
        long off = (long)(z - BATCH) * 65536;
        mm_body(zyh + off, zyl + off, 256, zcht + off, zclt + off, 256, 256,
                0, oh + off, ol + off, oht + off, olt + off, 256, 256, 0, 256, 1.f, 0.f,
                blockIdx.y * 128, blockIdx.x * 64, 1, smem);
    }
}

// ---------------- small kernels ----------------
__global__ __launch_bounds__(256) void pre_k(const float* __restrict__ pro) {
    int row = blockIdx.x;
    __shared__ float buf[HW];
    __shared__ float red[256];
    const float* p = pro + (long)row * HW;
    float s = 0.f;
    for (int i = threadIdx.x; i < HW; i += 256) { float v = p[i]; buf[i] = v; s += v; }
    red[threadIdx.x] = s;
    __syncthreads();
    for (int o = 128; o > 0; o >>= 1) {
        if (threadIdx.x < o) red[threadIdx.x] += red[threadIdx.x + o];
        __syncthreads();
    }
    float m = red[0] * (1.0f / HW);
    if (threadIdx.x == 0) g_mean[row] = m;
    long base = (long)row * KXC;
    for (int i = threadIdx.x; i < KXC; i += 256) {
        float v = (i < HW) ? buf[i] - m : 0.f;
        bf h = bhi(v);
        g_xch[base + i] = h;
        g_xcl[base + i] = blo(v, h);
    }
}

__global__ __launch_bounds__(256) void att_k(const float* __restrict__ w1,
                                             const float* __restrict__ w2,
                                             float* __restrict__ satt) {
    int b = blockIdx.x;
    __shared__ float gs[256], hs[16], av[256];
    gs[threadIdx.x] = g_mean[b * 256 + threadIdx.x];
    __syncthreads();
    if (threadIdx.x < 16) {
        float s = 0.f;
        const float* wr = w1 + threadIdx.x * 256;
        for (int c = 0; c < 256; c++) s += wr[c] * gs[c];
        hs[threadIdx.x] = s;
    }
    __syncthreads();
    float s = 0.f;
    const float* wr = w2 + threadIdx.x * 16;
#pragma unroll
    for (int c = 0; c < 16; c++) s += wr[c] * hs[c];
    float a = 1.0f / (1.0f + expf(-s));
    av[threadIdx.x] = a;
    g_attv[b * 256 + threadIdx.x] = a;
    __syncthreads();
    float* out = satt + (long)b * 65536;
    float aj = av[threadIdx.x];
    for (int i = 0; i < 256; i++) out[i * 256 + threadIdx.x] = av[i] * aj;
}

__global__ __launch_bounds__(256) void trace_k(const float* __restrict__ Aout) {
    int b = blockIdx.x, t = threadIdx.x;
    __shared__ float sm[256];
    sm[t] = Aout[(long)b * 65536 + t * 257];
    __syncthreads();
    for (int o = 128; o > 0; o >>= 1) {
        if (t < o) sm[t] += sm[t + o];
        __syncthreads();
    }
    if (t == 0) g_tr[b] = sm[0];
}

// iter0: Ypre planes; ZY0 planes (symmetric); L zero.
__global__ __launch_bounds__(256) void init_k(const float* __restrict__ Aout,
                                              float e1b, float e2b2) {
    int row = blockIdx.x;
    int b = row >> 8, i = row & 255;
    int j = threadIdx.x;
    long idx = (long)row * 256 + j;
    float y = Aout[idx] / g_tr[b];
    float ai = g_attv[(b << 8) + i], aj = g_attv[(b << 8) + j];
    float j1 = (i == j) ? y * (1.0f - e1b) : y;
    float j2 = y * (1.0f - e2b2 * (1.0f - ai * aj));
    float yp = y + 0.5f * (j1 - y) + 0.5f * (j2 - y);
    float zy = ((i == j) ? 1.5f : 0.0f) - 0.5f * y;
    bf h = bhi(yp);
    g_ypreh[idx] = h;
    g_yprel[idx] = blo(yp, h);
    bf hz = bhi(zy);
    g_zy0h[idx] = hz;
    g_zy0l[idx] = blo(zy, hz);
    g_L1[idx] = 0.f;
    g_L2[idx] = 0.f;
}

// fused: reconstruct J_prev from (Yold, L), L-update, ew1(i), Y split + transpose-split
__global__ __launch_bounds__(256) void ewf_k(
    const float* __restrict__ Ynew, const float* __restrict__ Yold, int useTr,
    float m1p, float e1p, float d1p, float c2p,
    float e1i, float d1i, float c2i, float e3, float mui) {
    __shared__ bf sh[64][80], sl[64][80];
    int b = blockIdx.z, i0 = blockIdx.y * 64, j0 = blockIdx.x * 64;
    int rl = threadIdx.x >> 2, sg = threadIdx.x & 3;
    int gi = i0 + rl, jb = j0 + sg * 16;
    long base = ((long)b * 256 + gi) * 256 + jb;
    float ai = g_attv[(b << 8) + gi];
    float yscale = useTr ? (1.0f / g_tr[b]) : 1.0f;
    float yn[16], yo[16], l1v[16], l2v[16];
#pragma unroll
    for (int q = 0; q < 4; q++) {
        *(float4*)(yn + q * 4) = *(const float4*)(Ynew + base + q * 4);
        *(float4*)(yo + q * 4) = *(const float4*)(Yold + base + q * 4);
        *(float4*)(l1v + q * 4) = *(const float4*)(g_L1 + base + q * 4);
        *(float4*)(l2v + q * 4) = *(const float4*)(g_L2 + base + q * 4);
    }
    __align__(16) bf hv[16], lv[16];
#pragma unroll
    for (int k = 0; k < 16; k++) {
        int gj = jb + k;
        float aj = g_attv[(b << 8) + gj];
        float s = 1.0f - ai * aj;
        float yov = yo[k] * yscale;
        float j1p = yov - e1p * l1v[k];
        if (gi == gj) j1p *= d1p;
        float j2p = (yov - e1p * l2v[k]) * (1.0f - c2p * s);
        float L1n = 0.9f * l1v[k] + m1p * (j1p - yn[k]);
        float L2n = 0.9f * l2v[k] + m1p * (j2p - yn[k]);
        float j1 = yn[k] - e1i * L1n;
        if (gi == gj) j1 *= d1i;
        float j2 = (yn[k] - e1i * L2n) * (1.0f - c2i * s);
        float yp = yn[k] + e3 * (mui * (j1 - yn[k]) + mui * (j2 - yn[k]) + L1n + L2n);
        l1v[k] = L1n; l2v[k] = L2n;
        bf h = bhi(yp);
        hv[k] = h;
        lv[k] = blo(yp, h);
        sh[sg * 16 + k][rl] = hv[k];
        sl[sg * 16 + k][rl] = lv[k];
    }
#pragma unroll
    for (int q = 0; q < 4; q++) {
        *(float4*)(g_L1 + base + q * 4) = *(float4*)(l1v + q * 4);
        *(float4*)(g_L2 + base + q * 4) = *(float4*)(l2v + q * 4);
    }
    *(uint4*)(g_yh + base) = *(uint4*)hv;
    *(uint4*)(g_yh + base + 8) = *(uint4*)(hv + 8);
    *(uint4*)(g_yl + base) = *(uint4*)lv;
    *(uint4*)(g_yl + base + 8) = *(uint4*)(lv + 8);
    __syncthreads();
    long tbase = ((long)b * 256 + j0 + rl) * 256 + i0 + sg * 16;
    *(uint4*)(g_yht + tbase) = *(uint4*)&sh[rl][sg * 16];
    *(uint4*)(g_yht + tbase + 8) = *(uint4*)&sh[rl][sg * 16 + 8];
    *(uint4*)(g_ylt + tbase) = *(uint4*)&sl[rl][sg * 16];
    *(uint4*)(g_ylt + tbase + 8) = *(uint4*)&sl[rl][sg * 16 + 8];
}

__global__ __launch_bounds__(256) void feat_k(const float* __restrict__ Yfin) {
    int row = blockIdx.x;
    int b = row >> 8, r = row & 255;
    float s = sqrtf(g_tr[b]);
    long base = (long)b * TRIL + (long)r * (r + 1) / 2;
    const float* yr = Yfin + (long)row * 256;
    for (int c = threadIdx.x; c <= r; c += 256) {
        float v = yr[c] * s;
        bf h = bhi(v);
        g_feath[base + c] = h;
        g_featl[base + c] = blo(v, h);
    }
}

__global__ __launch_bounds__(256) void fcwcvt_k(const float* __restrict__ fcw) {
    long i = ((long)blockIdx.x * 256 + threadIdx.x) * 4;
    float4 v = *(const float4*)(fcw + i);
    bf h0 = bhi(v.x), h1 = bhi(v.y), h2 = bhi(v.z), h3 = bhi(v.w);
    __nv_bfloat162 a0, a1, b0, b1;
    a0.x = h0; a0.y = h1; a1.x = h2; a1.y = h3;
    b0.x = blo(v.x, h0); b0.y = blo(v.y, h1);
    b1.x = blo(v.z, h2); b1.y = blo(v.w, h3);
    *(uint2*)(g_fcwh + i) = make_uint2(*(uint32_t*)&a0, *(uint32_t*)&a1);
    *(uint2*)(g_fcwl + i) = make_uint2(*(uint32_t*)&b0, *(uint32_t*)&b1);
}

__global__ __launch_bounds__(256) void fcred_k(const float* __restrict__ fcb,
                                               float* __restrict__ cls) {
    int i = blockIdx.x * 256 + threadIdx.x;
    if (i >= BATCH * 200) return;
    int b = i / 200, o = i % 200;
    float s = fcb[o];
#pragma unroll
    for (int sp = 0; sp < FC_SPLITS; sp++)
        s += g_fcp[sp * (BATCH * 256) + b * 256 + o];
    cls[i] = s;
}

// ---------------- driver ----------------
extern "C" void kernel_launch(void* const* d_in, const int* in_sizes, int n_in,
                              void* d_out, int out_size) {
    const float* pro = (const float*)d_in[0];
    const float* w1  = (const float*)d_in[1];
    const float* w2  = (const float*)d_in[2];
    const float* fcw = (const float*)d_in[3];
    const float* fcb = (const float*)d_in[4];
    float* out = (float*)d_out;
    float* cls  = out;
    float* Aout = out + BATCH * 200;
    float* satt = Aout + MAT;

    bf *xch, *xcl, *ypreh, *yprel, *zy0h, *zy0l;
    bf *yh, *yl, *yht, *ylt, *zyh, *zyl, *zyht, *zylt;
    bf *zah, *zal, *zaht, *zalt, *zbh, *zbl, *zbht, *zblt;
    bf *feath, *featl, *fcwh, *fcwl;
    float *Ya, *Yb, *fcp;
    cudaGetSymbolAddress((void**)&xch, g_xch);
    cudaGetSymbolAddress((void**)&xcl, g_xcl);
    cudaGetSymbolAddress((void**)&ypreh, g_ypreh);
    cudaGetSymbolAddress((void**)&yprel, g_yprel);
    cudaGetSymbolAddress((void**)&zy0h, g_zy0h);
    cudaGetSymbolAddress((void**)&zy0l, g_zy0l);
    cudaGetSymbolAddress((void**)&yh, g_yh);
    cudaGetSymbolAddress((void**)&yl, g_yl);
    cudaGetSymbolAddress((void**)&yht, g_yht);
    cudaGetSymbolAddress((void**)&ylt, g_ylt);
    cudaGetSymbolAddress((void**)&zyh, g_zyh);
    cudaGetSymbolAddress((void**)&zyl, g_zyl);
    cudaGetSymbolAddress((void**)&zyht, g_zyht);
    cudaGetSymbolAddress((void**)&zylt, g_zylt);
    cudaGetSymbolAddress((void**)&zah, g_zah);
    cudaGetSymbolAddress((void**)&zal, g_zal);
    cudaGetSymbolAddress((void**)&zaht, g_zaht);
    cudaGetSymbolAddress((void**)&zalt, g_zalt);
    cudaGetSymbolAddress((void**)&zbh, g_zbh);
    cudaGetSymbolAddress((void**)&zbl, g_zbl);
    cudaGetSymbolAddress((void**)&zbht, g_zbht);
    cudaGetSymbolAddress((void**)&zblt, g_zblt);
    cudaGetSymbolAddress((void**)&feath, g_feath);
    cudaGetSymbolAddress((void**)&featl, g_featl);
    cudaGetSymbolAddress((void**)&fcwh, g_fcwh);
    cudaGetSymbolAddress((void**)&fcwl, g_fcwl);
    cudaGetSymbolAddress((void**)&Ya, g_Ya);
    cudaGetSymbolAddress((void**)&Yb, g_Yb);
    cudaGetSymbolAddress((void**)&fcp, g_fcp);

    cudaFuncSetAttribute(mm_k, cudaFuncAttributeMaxDynamicSharedMemorySize, MM_SMEM);
    cudaFuncSetAttribute(mmYZ_k, cudaFuncAttributeMaxDynamicSharedMemorySize, MM_SMEM);

    pre_k<<<BATCH * DD, 256>>>(pro);                 // 0
    att_k<<<BATCH, 256>>>(w1, w2, satt);             // 1
    fcwcvt_k<<<6425, 256>>>(fcw);                    // 2

    dim3 g42(4, 2, BATCH);
    // 3 (ncu-sampled): covariance (fp32 out, split operands)
    mm_k<<<g42, 256, MM_SMEM>>>(xch, xcl, (long)DD * KXC, KXC,
                          xch, xcl, (long)DD * KXC, KXC, 256,
                          Aout, nullptr, nullptr, nullptr, nullptr,
                          65536, 256, 256, KXC, 0, 1.0f / HW, 0.f, 0);
    trace_k<<<BATCH, 256>>>(Aout);

    double mu = 0.5;
    init_k<<<BATCH * DD, 256>>>(Aout, 2e-3f, 2e-3f);
    // Y0 = Ypre @ ZY0 (ZY0 symmetric: planes double as transposed planes) -> Ya
    mm_k<<<g42, 256, MM_SMEM>>>(ypreh, yprel, 65536, 256,
                          zy0h, zy0l, 65536, 256, 256,
                          Ya, nullptr, nullptr, nullptr, nullptr,
                          65536, 256, 256, 256, 0, 1.0f, 0.f, 0);
    double muPrev = mu;
    mu *= ROPH;

    float* ybuf[2] = { Ya, Yb };
    bf *zch = zy0h, *zcl = zy0l, *zcht = zy0h, *zclt = zy0l;
    dim3 eg(4, 4, BATCH);
    dim3 gyz(4, 2, 2 * BATCH);

    for (int i = 1; i < ITERN; i++) {
        double eta = 1.0 / mu, e3 = 1.0 / (2.0 * mu);
        double etap = 1.0 / muPrev;
        float* Ynew = ybuf[(i - 1) & 1];
        const float* Yold = (i == 1) ? Aout : ybuf[i & 1];
        ewf_k<<<eg, 256>>>(Ynew, Yold, (i == 1) ? 1 : 0,
                           (float)muPrev, (float)etap,
                           (float)(1.0 - 1e-3 * etap), (float)(1e-3 * etap),
                           (float)eta, (float)(1.0 - 1e-3 * eta), (float)(1e-3 * eta),
                           (float)e3, (float)mu);
        // ZY = 1.5I - 0.5 * Z @ Y
        mm_k<<<g42, 256, MM_SMEM>>>(zch, zcl, 65536, 256,
                              yht, ylt, 65536, 256, 256,
                              nullptr, zyh, zyl, zyht, zylt,
                              65536, 256, 256, 256, 0, -0.5f, 1.5f, 1);
        if (i != ITERN - 1) {
            bf* oh  = (i & 1) ? zah : zbh;
            bf* ol  = (i & 1) ? zal : zbl;
            bf* oht = (i & 1) ? zaht : zbht;
            bf* olt = (i & 1) ? zalt : zblt;
            // fused: Ynew = Y @ ZY (fp32) AND Znew = ZY @ Z (planes)
            mmYZ_k<<<gyz, 256, MM_SMEM>>>(yh, yl, zyht, zylt, ybuf[i & 1],
                                          zyh, zyl, zcht, zclt,
                                          oh, ol, oht, olt);
            zch = oh; zcl = ol; zcht = oht; zclt = olt;
        } else {
            mm_k<<<g42, 256, MM_SMEM>>>(yh, yl, 65536, 256,
                                  zyht, zylt, 65536, 256, 256,
                                  ybuf[i & 1], nullptr, nullptr, nullptr, nullptr,
                                  65536, 256, 256, 256, 0, 1.0f, 0.f, 0);
        }
        if (i < ITERN - 1) {
            muPrev = mu;
            mu *= ROPH;
        }
    }

    feat_k<<<BATCH * DD, 256>>>(ybuf[(ITERN - 1) & 1]);
    dim3 gfc(4, 1, FC_SPLITS);
    mm_k<<<gfc, 256, MM_SMEM>>>(feath, featl, 0, TRIL,
                          fcwh, fcwl, 0, TRIL, 200,
                          fcp, nullptr, nullptr, nullptr, nullptr,
                          (long)BATCH * 256, 256, 200, TRIL, FC_KSPAN, 1.0f, 0.f, 0);
    fcred_k<<<100, 256>>>(fcb, cls);
}

// round 16
// speedup vs baseline: 1.1588x; 1.1588x over previous
#include <cuda_runtime.h>
#include <cuda_bf16.h>
#include <math.h>
#include <stdint.h>

#define BATCH 128
#define DD 256
#define HW 784
#define KXC 832
#define ITERN 7
#define ROPH 1.05
#define MAT (BATCH * DD * DD)
#define TRIL 32896
#define FC_SPLITS 16
#define FC_KSPAN 2080

#define STAGE_BYTES 40960
#define TILE_BYTES 10240
#define MM_SMEM (2 * STAGE_BYTES)

typedef __nv_bfloat16 bf;

// ---------------- scratch ----------------
__device__ bf g_xch[BATCH * DD * KXC], g_xcl[BATCH * DD * KXC];
__device__ bf g_ypreh[MAT], g_yprel[MAT];
__device__ bf g_zy0h[MAT], g_zy0l[MAT];
__device__ bf g_yh[MAT], g_yl[MAT];
__device__ bf g_zyh[MAT], g_zyl[MAT];
__device__ bf g_zah[MAT], g_zal[MAT];
__device__ bf g_zbh[MAT], g_zbl[MAT];
__device__ bf g_feath[BATCH * TRIL], g_featl[BATCH * TRIL];
__device__ bf g_fcwh[200 * TRIL], g_fcwl[200 * TRIL];
__device__ float g_Ya[MAT], g_Yb[MAT], g_L1[MAT], g_L2[MAT];
__device__ float g_mean[BATCH * DD], g_attv[BATCH * DD], g_tr[BATCH];
__device__ float g_fcp[FC_SPLITS * BATCH * 256];

#define DEVINL __device__ __forceinline__
DEVINL uint32_t s2u(const void* p) {
    uint32_t a;
    asm("{ .reg .u64 t; cvta.to.shared.u64 t, %1; cvt.u32.u64 %0, t; }" : "=r"(a) : "l"(p));
    return a;
}
DEVINL void ldmA(uint32_t* a, uint32_t addr) {
    asm volatile("ldmatrix.sync.aligned.m8n8.x4.shared.b16 {%0,%1,%2,%3}, [%4];"
                 : "=r"(a[0]), "=r"(a[1]), "=r"(a[2]), "=r"(a[3]) : "r"(addr));
}
DEVINL void ldmB(uint32_t* b, uint32_t addr) {
    asm volatile("ldmatrix.sync.aligned.m8n8.x2.shared.b16 {%0,%1}, [%2];"
                 : "=r"(b[0]), "=r"(b[1]) : "r"(addr));
}
DEVINL void mma16816(float* c, const uint32_t* a, const uint32_t* b2) {
    asm volatile(
        "mma.sync.aligned.m16n8k16.row.col.f32.bf16.bf16.f32 "
        "{%0,%1,%2,%3}, {%4,%5,%6,%7}, {%8,%9}, {%0,%1,%2,%3};"
        : "+f"(c[0]), "+f"(c[1]), "+f"(c[2]), "+f"(c[3])
        : "r"(a[0]), "r"(a[1]), "r"(a[2]), "r"(a[3]), "r"(b2[0]), "r"(b2[1]));
}
DEVINL void cpa16(uint32_t dst, const void* src, int pred) {
    asm volatile("cp.async.cg.shared.global [%0], [%1], 16, %2;"
                 :: "r"(dst), "l"(src), "r"(pred ? 16 : 0) : "memory");
}
#define CPA_COMMIT() asm volatile("cp.async.commit_group;" ::: "memory")
#define CPA_WAIT(n)  asm volatile("cp.async.wait_group %0;" :: "n"(n) : "memory")

DEVINL bf bhi(float v) { return __float2bfloat16(v); }
DEVINL bf blo(float v, bf h) { return __float2bfloat16(v - __bfloat162float(h)); }

// ---------------- split-bf16 HMMA GEMM body (CTA 128x128, 2-stage) --------
// C[m,n] = alpha * sum_k (Ah+Al)[m,k]*(Bh+Bl)[n,k] + diag*(m==n)
// 8 warps: 2M x 4N, warp tile 64x32.
// epi 0: fp32 out; epi 1: bf16 hi/lo planes (NO transpose — outputs symmetric).
DEVINL void mm_body(
    const bf* __restrict__ Ah, const bf* __restrict__ Al, int lda,
    const bf* __restrict__ Bh, const bf* __restrict__ Bl, int ldb, int nbValid,
    float* __restrict__ cf, bf* __restrict__ ch, bf* __restrict__ cl,
    int ldc, int nlimit, int k0, int k1, float alpha, float diag,
    int rowBase, int colBase, int epi, char* smem) {
    int tid = threadIdx.x;
    int lane = tid & 31, wid = tid >> 5;
    int warpM = wid >> 2, warpN = wid & 3;

    float acc[4][4][4];
#pragma unroll
    for (int a = 0; a < 4; a++)
#pragma unroll
        for (int b = 0; b < 4; b++)
#pragma unroll
            for (int c = 0; c < 4; c++) acc[a][b][c] = 0.f;

    uint32_t smemB = s2u(smem);
    int nsteps = (k1 - k0) >> 5;
    const bf* planes[4] = { Ah, Al, Bh, Bl };

#define STAGE_LOAD(stg, kt)                                                   \
    do {                                                                      \
        uint32_t base = smemB + (stg) * STAGE_BYTES;                          \
        _Pragma("unroll")                                                     \
        for (int p = 0; p < 8; p++) {                                         \
            int idx = tid + p * 256;                                          \
            int tile = idx >> 9, r = (idx >> 2) & 127, s = idx & 3;           \
            int pred = 1;                                                     \
            long grow_;                                                       \
            int ld_;                                                          \
            if (tile < 2) { grow_ = rowBase + r; ld_ = lda; }                 \
            else { grow_ = colBase + r; ld_ = ldb; pred = (colBase + r < nbValid); } \
            const bf* srcp = planes[tile] + grow_ * ld_ + (kt) + s * 8;       \
            cpa16(base + tile * TILE_BYTES + r * 80 + s * 16, srcp, pred);    \
        }                                                                     \
        CPA_COMMIT();                                                         \
    } while (0)

    STAGE_LOAD(0, k0);

    for (int i = 0; i < nsteps; i++) {
        int stg = i & 1;
        if (i + 1 < nsteps) {
            STAGE_LOAD(stg ^ 1, k0 + (i + 1) * 32);
            CPA_WAIT(1);
        } else {
            CPA_WAIT(0);
        }
        __syncthreads();
        uint32_t sbA = smemB + stg * STAGE_BYTES;
        uint32_t sbAl = sbA + TILE_BYTES;
        uint32_t sbBh = sbA + 2 * TILE_BYTES;
        uint32_t sbBl = sbA + 3 * TILE_BYTES;
#pragma unroll
        for (int kk = 0; kk < 2; kk++) {
            uint32_t afh[4][4], afl[4][4], bfh[4][2], bfl[4][2];
#pragma unroll
            for (int mi = 0; mi < 4; mi++) {
                int r = warpM * 64 + mi * 16 + (lane & 15);
                ldmA(afh[mi], sbA + r * 80 + kk * 32 + ((lane >> 4) * 16));
            }
#pragma unroll
            for (int ni = 0; ni < 4; ni++) {
                int r = warpN * 32 + ni * 8 + (lane & 7);
                ldmB(bfh[ni], sbBh + r * 80 + kk * 32 + (((lane >> 3) & 1) * 16));
            }
#pragma unroll
            for (int mi = 0; mi < 4; mi++)
#pragma unroll
                for (int ni = 0; ni < 4; ni++) mma16816(acc[mi][ni], afh[mi], bfh[ni]);
#pragma unroll
            for (int ni = 0; ni < 4; ni++) {
                int r = warpN * 32 + ni * 8 + (lane & 7);
                ldmB(bfl[ni], sbBl + r * 80 + kk * 32 + (((lane >> 3) & 1) * 16));
            }
#pragma unroll
            for (int mi = 0; mi < 4; mi++)
#pragma unroll
                for (int ni = 0; ni < 4; ni++) mma16816(acc[mi][ni], afh[mi], bfl[ni]);
#pragma unroll
            for (int mi = 0; mi < 4; mi++) {
                int r = warpM * 64 + mi * 16 + (lane & 15);
                ldmA(afl[mi], sbAl + r * 80 + kk * 32 + ((lane >> 4) * 16));
            }
#pragma unroll
            for (int mi = 0; mi < 4; mi++)
#pragma unroll
                for (int ni = 0; ni < 4; ni++) mma16816(acc[mi][ni], afl[mi], bfh[ni]);
        }
        __syncthreads();
    }
#undef STAGE_LOAD

    int g = lane >> 2, t4 = lane & 3;
#pragma unroll
    for (int mi = 0; mi < 4; mi++)
#pragma unroll
        for (int ni = 0; ni < 4; ni++) {
            float* c = acc[mi][ni];
            int col = colBase + warpN * 32 + ni * 8 + t4 * 2;
            if (col >= nlimit) continue;
#pragma unroll
            for (int h = 0; h < 2; h++) {
                int row = rowBase + warpM * 64 + mi * 16 + g + h * 8;
                float v0 = alpha * c[h * 2] + ((row == col) ? diag : 0.f);
                float v1 = alpha * c[h * 2 + 1] + ((row == col + 1) ? diag : 0.f);
                if (epi == 0) {
                    *(float2*)(cf + (long)row * ldc + col) = make_float2(v0, v1);
                } else {
                    bf h0 = bhi(v0), h1 = bhi(v1);
                    __nv_bfloat162 ph, pl;
                    ph.x = h0; ph.y = h1;
                    pl.x = blo(v0, h0); pl.y = blo(v1, h1);
                    *(__nv_bfloat162*)(ch + (long)row * ldc + col) = ph;
                    *(__nv_bfloat162*)(cl + (long)row * ldc + col) = pl;
                }
            }
        }
}

// generic wrapper: kspan==0 batched over blockIdx.z; kspan>0 split-K (fp32 out)
__global__ __launch_bounds__(256, 2) void mm_k(
    const bf* __restrict__ Agh, const bf* __restrict__ Agl, long aStr, int lda,
    const bf* __restrict__ Bgh, const bf* __restrict__ Bgl, long bStr, int ldb, int nbValid,
    float* __restrict__ Cf, bf* __restrict__ Ch, bf* __restrict__ Cl,
    long cStr, int ldc, int nlimit, int K, int kspan, float alpha, float diag, int epi) {
    extern __shared__ __align__(16) char smem[];
    int z = blockIdx.z;
    const bf *Ah = Agh, *Al = Agl, *Bh = Bgh, *Bl = Bgl;
    int k0 = 0, k1 = K;
    float* cf = 0;
    bf *ch = 0, *cl = 0;
    if (kspan) {
        k0 = z * kspan;
        k1 = min(K, k0 + kspan);
        cf = Cf + (long)z * cStr;
    } else {
        Ah += (long)z * aStr; Al += (long)z * aStr;
        Bh += (long)z * bStr; Bl += (long)z * bStr;
        if (epi == 0) cf = Cf + (long)z * cStr;
        else { ch = Ch + (long)z * cStr; cl = Cl + (long)z * cStr; }
    }
    mm_body(Ah, Al, lda, Bh, Bl, ldb, nbValid, cf, ch, cl,
            ldc, nlimit, k0, k1, alpha, diag,
            blockIdx.y * 128, blockIdx.x * 128, epi, smem);
}

// fused Ynew + Znew: z<BATCH -> Y = Y @ ZY (fp32); z>=BATCH -> Znew = ZY @ Z (planes)
// all B-operands use untransposed planes (symmetric matrices).
__global__ __launch_bounds__(256, 2) void mmYZ_k(
    const bf* __restrict__ yh, const bf* __restrict__ yl,
    const bf* __restrict__ zyh, const bf* __restrict__ zyl, float* __restrict__ Yout,
    const bf* __restrict__ zch, const bf* __restrict__ zcl,
    bf* __restrict__ oh, bf* __restrict__ ol) {
    extern __shared__ __align__(16) char smem[];
    int z = blockIdx.z;
    if (z < BATCH) {
        long off = (long)z * 65536;
        mm_body(yh + off, yl + off, 256, zyh + off, zyl + off, 256, 256,
                Yout + off, 0, 0, 256, 256, 0, 256, 1.f, 0.f,
                blockIdx.y * 128, blockIdx.x * 128, 0, smem);
    } else {
        long off = (long)(z - BATCH) * 65536;
        mm_body(zyh + off, zyl + off, 256, zch + off, zcl + off, 256, 256,
                0, oh + off, ol + off, 256, 256, 0, 256, 1.f, 0.f,
                blockIdx.y * 128, blockIdx.x * 128, 1, smem);
    }
}

// ---------------- small kernels ----------------
__global__ __launch_bounds__(256) void pre_k(const float* __restrict__ pro) {
    int row = blockIdx.x;
    __shared__ float buf[HW];
    __shared__ float red[256];
    const float* p = pro + (long)row * HW;
    float s = 0.f;
    for (int i = threadIdx.x; i < HW; i += 256) { float v = p[i]; buf[i] = v; s += v; }
    red[threadIdx.x] = s;
    __syncthreads();
    for (int o = 128; o > 0; o >>= 1) {
        if (threadIdx.x < o) red[threadIdx.x] += red[threadIdx.x + o];
        __syncthreads();
    }
    float m = red[0] * (1.0f / HW);
    if (threadIdx.x == 0) g_mean[row] = m;
    long base = (long)row * KXC;
    for (int i = threadIdx.x; i < KXC; i += 256) {
        float v = (i < HW) ? buf[i] - m : 0.f;
        bf h = bhi(v);
        g_xch[base + i] = h;
        g_xcl[base + i] = blo(v, h);
    }
}

__global__ __launch_bounds__(256) void att_k(const float* __restrict__ w1,
                                             const float* __restrict__ w2,
                                             float* __restrict__ satt) {
    int b = blockIdx.x;
    __shared__ float gs[256], hs[16], av[256];
    gs[threadIdx.x] = g_mean[b * 256 + threadIdx.x];
    __syncthreads();
    if (threadIdx.x < 16) {
        float s = 0.f;
        const float* wr = w1 + threadIdx.x * 256;
        for (int c = 0; c < 256; c++) s += wr[c] * gs[c];
        hs[threadIdx.x] = s;
    }
    __syncthreads();
    float s = 0.f;
    const float* wr = w2 + threadIdx.x * 16;
#pragma unroll
    for (int c = 0; c < 16; c++) s += wr[c] * hs[c];
    float a = 1.0f / (1.0f + expf(-s));
    av[threadIdx.x] = a;
    g_attv[b * 256 + threadIdx.x] = a;
    __syncthreads();
    float* out = satt + (long)b * 65536;
    float aj = av[threadIdx.x];
    for (int i = 0; i < 256; i++) out[i * 256 + threadIdx.x] = av[i] * aj;
}

__global__ __launch_bounds__(256) void trace_k(const float* __restrict__ Aout) {
    int b = blockIdx.x, t = threadIdx.x;
    __shared__ float sm[256];
    sm[t] = Aout[(long)b * 65536 + t * 257];
    __syncthreads();
    for (int o = 128; o > 0; o >>= 1) {
        if (t < o) sm[t] += sm[t + o];
        __syncthreads();
    }
    if (t == 0) g_tr[b] = sm[0];
}

// iter0: Ypre planes; ZY0 planes (symmetric); L zero.
__global__ __launch_bounds__(256) void init_k(const float* __restrict__ Aout,
                                              float e1b, float e2b2) {
    int row = blockIdx.x;
    int b = row >> 8, i = row & 255;
    int j = threadIdx.x;
    long idx = (long)row * 256 + j;
    float y = Aout[idx] / g_tr[b];
    float ai = g_attv[(b << 8) + i], aj = g_attv[(b << 8) + j];
    float j1 = (i == j) ? y * (1.0f - e1b) : y;
    float j2 = y * (1.0f - e2b2 * (1.0f - ai * aj));
    float yp = y + 0.5f * (j1 - y) + 0.5f * (j2 - y);
    float zy = ((i == j) ? 1.5f : 0.0f) - 0.5f * y;
    bf h = bhi(yp);
    g_ypreh[idx] = h;
    g_yprel[idx] = blo(yp, h);
    bf hz = bhi(zy);
    g_zy0h[idx] = hz;
    g_zy0l[idx] = blo(zy, hz);
    g_L1[idx] = 0.f;
    g_L2[idx] = 0.f;
}

// fused: reconstruct J_prev from (Yold, L), L-update, ew1(i), Y split (no transpose)
__global__ __launch_bounds__(256) void ewf_k(
    const float* __restrict__ Ynew, const float* __restrict__ Yold, int useTr,
    float m1p, float e1p, float d1p, float c2p,
    float e1i, float d1i, float c2i, float e3, float mui) {
    int row = blockIdx.x;           // b*256 + i, 64 cols per 4-thread group
    int b = row >> 8, gi = row & 255;
    int sg = threadIdx.x & 15;      // 16 groups of 16 cols
    int rep = threadIdx.x >> 4;     // unused rows handled by grid: 16 rows per block? keep simple:
    (void)rep;
    // simple layout: 256 threads = 16 cols x 16 rows? Keep original: one row per block.
    int jb = sg * 16;
    // only threads 0..15 active per row would waste; use original mapping instead:
    // Recompute: use 256 threads covering 256 cols, 1 col each.
    int j = threadIdx.x;
    long idx = ((long)b * 256 + gi) * 256 + j;
    float ai = g_attv[(b << 8) + gi];
    float aj = g_attv[(b << 8) + j];
    float yscale = useTr ? (1.0f / g_tr[b]) : 1.0f;
    float yn = Ynew[idx];
    float yo = Yold[idx] * yscale;
    float l1 = g_L1[idx], l2 = g_L2[idx];
    float s = 1.0f - ai * aj;
    float j1p = yo - e1p * l1;
    if (gi == j) j1p *= d1p;
    float j2p = (yo - e1p * l2) * (1.0f - c2p * s);
    float L1n = 0.9f * l1 + m1p * (j1p - yn);
    float L2n = 0.9f * l2 + m1p * (j2p - yn);
    float j1 = yn - e1i * L1n;
    if (gi == j) j1 *= d1i;
    float j2 = (yn - e1i * L2n) * (1.0f - c2i * s);
    float yp = yn + e3 * (mui * (j1 - yn) + mui * (j2 - yn) + L1n + L2n);
    g_L1[idx] = L1n;
    g_L2[idx] = L2n;
    bf h = bhi(yp);
    g_yh[idx] = h;
    g_yl[idx] = blo(yp, h);
    (void)jb;
}

__global__ __launch_bounds__(256) void feat_k(const float* __restrict__ Yfin) {
    int row = blockIdx.x;
    int b = row >> 8, r = row & 255;
    float s = sqrtf(g_tr[b]);
    long base = (long)b * TRIL + (long)r * (r + 1) / 2;
    const float* yr = Yfin + (long)row * 256;
    for (int c = threadIdx.x; c <= r; c += 256) {
        float v = yr[c] * s;
        bf h = bhi(v);
        g_feath[base + c] = h;
        g_featl[base + c] = blo(v, h);
    }
}

__global__ __launch_bounds__(256) void fcwcvt_k(const float* __restrict__ fcw) {
    long i = ((long)blockIdx.x * 256 + threadIdx.x) * 4;
    float4 v = *(const float4*)(fcw + i);
    bf h0 = bhi(v.x), h1 = bhi(v.y), h2 = bhi(v.z), h3 = bhi(v.w);
    __nv_bfloat162 a0, a1, b0, b1;
    a0.x = h0; a0.y = h1; a1.x = h2; a1.y = h3;
    b0.x = blo(v.x, h0); b0.y = blo(v.y, h1);
    b1.x = blo(v.z, h2); b1.y = blo(v.w, h3);
    *(uint2*)(g_fcwh + i) = make_uint2(*(uint32_t*)&a0, *(uint32_t*)&a1);
    *(uint2*)(g_fcwl + i) = make_uint2(*(uint32_t*)&b0, *(uint32_t*)&b1);
}

__global__ __launch_bounds__(256) void fcred_k(const float* __restrict__ fcb,
                                               float* __restrict__ cls) {
    int i = blockIdx.x * 256 + threadIdx.x;
    if (i >= BATCH * 200) return;
    int b = i / 200, o = i % 200;
    float s = fcb[o];
#pragma unroll
    for (int sp = 0; sp < FC_SPLITS; sp++)
        s += g_fcp[sp * (BATCH * 256) + b * 256 + o];
    cls[i] = s;
}

// ---------------- driver ----------------
extern "C" void kernel_launch(void* const* d_in, const int* in_sizes, int n_in,
                              void* d_out, int out_size) {
    const float* pro = (const float*)d_in[0];
    const float* w1  = (const float*)d_in[1];
    const float* w2  = (const float*)d_in[2];
    const float* fcw = (const float*)d_in[3];
    const float* fcb = (const float*)d_in[4];
    float* out = (float*)d_out;
    float* cls  = out;
    float* Aout = out + BATCH * 200;
    float* satt = Aout + MAT;

    bf *xch, *xcl, *ypreh, *yprel, *zy0h, *zy0l;
    bf *yh, *yl, *zyh, *zyl, *zah, *zal, *zbh, *zbl;
    bf *feath, *featl, *fcwh, *fcwl;
    float *Ya, *Yb, *fcp;
    cudaGetSymbolAddress((void**)&xch, g_xch);
    cudaGetSymbolAddress((void**)&xcl, g_xcl);
    cudaGetSymbolAddress((void**)&ypreh, g_ypreh);
    cudaGetSymbolAddress((void**)&yprel, g_yprel);
    cudaGetSymbolAddress((void**)&zy0h, g_zy0h);
    cudaGetSymbolAddress((void**)&zy0l, g_zy0l);
    cudaGetSymbolAddress((void**)&yh, g_yh);
    cudaGetSymbolAddress((void**)&yl, g_yl);
    cudaGetSymbolAddress((void**)&zyh, g_zyh);
    cudaGetSymbolAddress((void**)&zyl, g_zyl);
    cudaGetSymbolAddress((void**)&zah, g_zah);
    cudaGetSymbolAddress((void**)&zal, g_zal);
    cudaGetSymbolAddress((void**)&zbh, g_zbh);
    cudaGetSymbolAddress((void**)&zbl, g_zbl);
    cudaGetSymbolAddress((void**)&feath, g_feath);
    cudaGetSymbolAddress((void**)&featl, g_featl);
    cudaGetSymbolAddress((void**)&fcwh, g_fcwh);
    cudaGetSymbolAddress((void**)&fcwl, g_fcwl);
    cudaGetSymbolAddress((void**)&Ya, g_Ya);
    cudaGetSymbolAddress((void**)&Yb, g_Yb);
    cudaGetSymbolAddress((void**)&fcp, g_fcp);

    cudaFuncSetAttribute(mm_k, cudaFuncAttributeMaxDynamicSharedMemorySize, MM_SMEM);
    cudaFuncSetAttribute(mmYZ_k, cudaFuncAttributeMaxDynamicSharedMemorySize, MM_SMEM);

    pre_k<<<BATCH * DD, 256>>>(pro);                 // 0
    att_k<<<BATCH, 256>>>(w1, w2, satt);             // 1
    fcwcvt_k<<<6425, 256>>>(fcw);                    // 2

    dim3 g22(2, 2, BATCH);
    // 3 (ncu-sampled): covariance (fp32 out, split operands)
    mm_k<<<g22, 256, MM_SMEM>>>(xch, xcl, (long)DD * KXC, KXC,
                          xch, xcl, (long)DD * KXC, KXC, 256,
                          Aout, nullptr, nullptr,
                          65536, 256, 256, KXC, 0, 1.0f / HW, 0.f, 0);
    trace_k<<<BATCH, 256>>>(Aout);

    double mu = 0.5;
    init_k<<<BATCH * DD, 256>>>(Aout, 2e-3f, 2e-3f);
    // Y0 = Ypre @ ZY0 -> Ya
    mm_k<<<g22, 256, MM_SMEM>>>(ypreh, yprel, 65536, 256,
                          zy0h, zy0l, 65536, 256, 256,
                          Ya, nullptr, nullptr,
                          65536, 256, 256, 256, 0, 1.0f, 0.f, 0);
    double muPrev = mu;
    mu *= ROPH;

    float* ybuf[2] = { Ya, Yb };
    bf *zch = zy0h, *zcl = zy0l;
    dim3 gyz(2, 2, 2 * BATCH);

    for (int i = 1; i < ITERN; i++) {
        double eta = 1.0 / mu, e3 = 1.0 / (2.0 * mu);
        double etap = 1.0 / muPrev;
        float* Ynew = ybuf[(i - 1) & 1];
        const float* Yold = (i == 1) ? Aout : ybuf[i & 1];
        ewf_k<<<BATCH * DD, 256>>>(Ynew, Yold, (i == 1) ? 1 : 0,
                           (float)muPrev, (float)etap,
                           (float)(1.0 - 1e-3 * etap), (float)(1e-3 * etap),
                           (float)eta, (float)(1.0 - 1e-3 * eta), (float)(1e-3 * eta),
                           (float)e3, (float)mu);
        // ZY = 1.5I - 0.5 * Z @ Y   (B = Y, symmetric)
        mm_k<<<g22, 256, MM_SMEM>>>(zch, zcl, 65536, 256,
                              yh, yl, 65536, 256, 256,
                              nullptr, zyh, zyl,
                              65536, 256, 256, 256, 0, -0.5f, 1.5f, 1);
        if (i != ITERN - 1) {
            bf* oh = (i & 1) ? zah : zbh;
            bf* ol = (i & 1) ? zal : zbl;
            // fused: Ynew = Y @ ZY (fp32) AND Znew = ZY @ Z (planes)
            mmYZ_k<<<gyz, 256, MM_SMEM>>>(yh, yl, zyh, zyl, ybuf[i & 1],
                                          zch, zcl, oh, ol);
            zch = oh; zcl = ol;
        } else {
            mm_k<<<g22, 256, MM_SMEM>>>(yh, yl, 65536, 256,
                                  zyh, zyl, 65536, 256, 256,
                                  ybuf[i & 1], nullptr, nullptr,
                                  65536, 256, 256, 256, 0, 1.0f, 0.f, 0);
        }
        if (i < ITERN - 1) {
            muPrev = mu;
            mu *= ROPH;
        }
    }

    feat_k<<<BATCH * DD, 256>>>(ybuf[(ITERN - 1) & 1]);
    dim3 gfc(2, 1, FC_SPLITS);
    mm_k<<<gfc, 256, MM_SMEM>>>(feath, featl, 0, TRIL,
                          fcwh, fcwl, 0, TRIL, 200,
                          fcp, nullptr, nullptr,
                          (long)BATCH * 256, 256, 200, TRIL, FC_KSPAN, 1.0f, 0.f, 0);
    fcred_k<<<100, 256>>>(fcb, cls);
}

// round 17
// speedup vs baseline: 1.2680x; 1.0943x over previous
#include <cuda_runtime.h>
#include <cuda_bf16.h>
#include <math.h>
#include <stdint.h>

#define BATCH 128
#define DD 256
#define HW 784
#define KXC 800
#define ITERN 7
#define ROPH 1.05
#define MAT (BATCH * DD * DD)
#define TRIL 32896
#define FC_SPLITS 16
#define FC_KSPAN 2080

#define STAGE_BYTES 40960
#define TILE_BYTES 10240
#define MM_SMEM (2 * STAGE_BYTES)

typedef __nv_bfloat16 bf;

// ---------------- scratch ----------------
__device__ bf g_xch[BATCH * DD * KXC], g_xcl[BATCH * DD * KXC];
__device__ bf g_ypreh[MAT], g_yprel[MAT];
__device__ bf g_zy0h[MAT], g_zy0l[MAT];
__device__ bf g_yh[MAT], g_yl[MAT];
__device__ bf g_zyh[MAT], g_zyl[MAT];
__device__ bf g_zah[MAT], g_zal[MAT];
__device__ bf g_zbh[MAT], g_zbl[MAT];
__device__ bf g_feath[BATCH * TRIL], g_featl[BATCH * TRIL];
__device__ bf g_fcwh[200 * TRIL], g_fcwl[200 * TRIL];
__device__ float g_Ya[MAT], g_Yb[MAT], g_L1[MAT], g_L2[MAT];
__device__ float g_mean[BATCH * DD], g_attv[BATCH * DD], g_tr[BATCH];
__device__ float g_fcp[FC_SPLITS * BATCH * 256];

#define DEVINL __device__ __forceinline__
DEVINL uint32_t s2u(const void* p) {
    uint32_t a;
    asm("{ .reg .u64 t; cvta.to.shared.u64 t, %1; cvt.u32.u64 %0, t; }" : "=r"(a) : "l"(p));
    return a;
}
DEVINL void ldmA(uint32_t* a, uint32_t addr) {
    asm volatile("ldmatrix.sync.aligned.m8n8.x4.shared.b16 {%0,%1,%2,%3}, [%4];"
                 : "=r"(a[0]), "=r"(a[1]), "=r"(a[2]), "=r"(a[3]) : "r"(addr));
}
DEVINL void ldmB(uint32_t* b, uint32_t addr) {
    asm volatile("ldmatrix.sync.aligned.m8n8.x2.shared.b16 {%0,%1}, [%2];"
                 : "=r"(b[0]), "=r"(b[1]) : "r"(addr));
}
DEVINL void mma16816(float* c, const uint32_t* a, const uint32_t* b2) {
    asm volatile(
        "mma.sync.aligned.m16n8k16.row.col.f32.bf16.bf16.f32 "
        "{%0,%1,%2,%3}, {%4,%5,%6,%7}, {%8,%9}, {%0,%1,%2,%3};"
        : "+f"(c[0]), "+f"(c[1]), "+f"(c[2]), "+f"(c[3])
        : "r"(a[0]), "r"(a[1]), "r"(a[2]), "r"(a[3]), "r"(b2[0]), "r"(b2[1]));
}
DEVINL void cpa16(uint32_t dst, const void* src, int pred) {
    asm volatile("cp.async.cg.shared.global [%0], [%1], 16, %2;"
                 :: "r"(dst), "l"(src), "r"(pred ? 16 : 0) : "memory");
}
#define CPA_COMMIT() asm volatile("cp.async.commit_group;" ::: "memory")
#define CPA_WAIT(n)  asm volatile("cp.async.wait_group %0;" :: "n"(n) : "memory")

DEVINL bf bhi(float v) { return __float2bfloat16(v); }
DEVINL bf blo(float v, bf h) { return __float2bfloat16(v - __bfloat162float(h)); }

// ---------------- split-bf16 HMMA GEMM body (CTA 128x128, 2-stage) --------
// C[m,n] = alpha * sum_k (Ah+Al)[m,k]*(Bh+Bl)[n,k] + diag*(m==n)
// epi 0: fp32 out; epi 1: bf16 hi/lo planes.
// mirror: additionally write C^T block (symmetric outputs, off-diag blocks).
DEVINL void mm_body(
    const bf* __restrict__ Ah, const bf* __restrict__ Al, int lda,
    const bf* __restrict__ Bh, const bf* __restrict__ Bl, int ldb, int nbValid,
    float* __restrict__ cf, bf* __restrict__ ch, bf* __restrict__ cl,
    int ldc, int nlimit, int k0, int k1, float alpha, float diag,
    int rowBase, int colBase, int epi, int mirror, char* smem) {
    int tid = threadIdx.x;
    int lane = tid & 31, wid = tid >> 5;
    int warpM = wid >> 2, warpN = wid & 3;

    float acc[4][4][4];
#pragma unroll
    for (int a = 0; a < 4; a++)
#pragma unroll
        for (int b = 0; b < 4; b++)
#pragma unroll
            for (int c = 0; c < 4; c++) acc[a][b][c] = 0.f;

    uint32_t smemB = s2u(smem);
    int nsteps = (k1 - k0) >> 5;
    const bf* planes[4] = { Ah, Al, Bh, Bl };

#define STAGE_LOAD(stg, kt)                                                   \
    do {                                                                      \
        uint32_t base = smemB + (stg) * STAGE_BYTES;                          \
        _Pragma("unroll")                                                     \
        for (int p = 0; p < 8; p++) {                                         \
            int idx = tid + p * 256;                                          \
            int tile = idx >> 9, r = (idx >> 2) & 127, s = idx & 3;           \
            int pred = 1;                                                     \
            long grow_;                                                       \
            int ld_;                                                          \
            if (tile < 2) { grow_ = rowBase + r; ld_ = lda; }                 \
            else { grow_ = colBase + r; ld_ = ldb; pred = (colBase + r < nbValid); } \
            const bf* srcp = planes[tile] + grow_ * ld_ + (kt) + s * 8;       \
            cpa16(base + tile * TILE_BYTES + r * 80 + s * 16, srcp, pred);    \
        }                                                                     \
        CPA_COMMIT();                                                         \
    } while (0)

    STAGE_LOAD(0, k0);

    for (int i = 0; i < nsteps; i++) {
        int stg = i & 1;
        if (i + 1 < nsteps) {
            STAGE_LOAD(stg ^ 1, k0 + (i + 1) * 32);
            CPA_WAIT(1);
        } else {
            CPA_WAIT(0);
        }
        __syncthreads();
        uint32_t sbA = smemB + stg * STAGE_BYTES;
        uint32_t sbAl = sbA + TILE_BYTES;
        uint32_t sbBh = sbA + 2 * TILE_BYTES;
        uint32_t sbBl = sbA + 3 * TILE_BYTES;
#pragma unroll
        for (int kk = 0; kk < 2; kk++) {
            uint32_t afh[4][4], afl[4][4], bfh[4][2], bfl[4][2];
#pragma unroll
            for (int mi = 0; mi < 4; mi++) {
                int r = warpM * 64 + mi * 16 + (lane & 15);
                ldmA(afh[mi], sbA + r * 80 + kk * 32 + ((lane >> 4) * 16));
            }
#pragma unroll
            for (int ni = 0; ni < 4; ni++) {
                int r = warpN * 32 + ni * 8 + (lane & 7);
                ldmB(bfh[ni], sbBh + r * 80 + kk * 32 + (((lane >> 3) & 1) * 16));
            }
#pragma unroll
            for (int mi = 0; mi < 4; mi++)
#pragma unroll
                for (int ni = 0; ni < 4; ni++) mma16816(acc[mi][ni], afh[mi], bfh[ni]);
#pragma unroll
            for (int ni = 0; ni < 4; ni++) {
                int r = warpN * 32 + ni * 8 + (lane & 7);
                ldmB(bfl[ni], sbBl + r * 80 + kk * 32 + (((lane >> 3) & 1) * 16));
            }
#pragma unroll
            for (int mi = 0; mi < 4; mi++)
#pragma unroll
                for (int ni = 0; ni < 4; ni++) mma16816(acc[mi][ni], afh[mi], bfl[ni]);
#pragma unroll
            for (int mi = 0; mi < 4; mi++) {
                int r = warpM * 64 + mi * 16 + (lane & 15);
                ldmA(afl[mi], sbAl + r * 80 + kk * 32 + ((lane >> 4) * 16));
            }
#pragma unroll
            for (int mi = 0; mi < 4; mi++)
#pragma unroll
                for (int ni = 0; ni < 4; ni++) mma16816(acc[mi][ni], afl[mi], bfh[ni]);
        }
        __syncthreads();
    }
#undef STAGE_LOAD

    int g = lane >> 2, t4 = lane & 3;
#pragma unroll
    for (int mi = 0; mi < 4; mi++)
#pragma unroll
        for (int ni = 0; ni < 4; ni++) {
            float* c = acc[mi][ni];
            int col = colBase + warpN * 32 + ni * 8 + t4 * 2;
            if (col >= nlimit) continue;
#pragma unroll
            for (int h = 0; h < 2; h++) {
                int row = rowBase + warpM * 64 + mi * 16 + g + h * 8;
                float v0 = alpha * c[h * 2] + ((row == col) ? diag : 0.f);
                float v1 = alpha * c[h * 2 + 1] + ((row == col + 1) ? diag : 0.f);
                if (epi == 0) {
                    *(float2*)(cf + (long)row * ldc + col) = make_float2(v0, v1);
                    if (mirror) {
                        cf[(long)col * ldc + row] = v0;
                        cf[(long)(col + 1) * ldc + row] = v1;
                    }
                } else {
                    bf h0 = bhi(v0), h1 = bhi(v1);
                    bf q0 = blo(v0, h0), q1 = blo(v1, h1);
                    __nv_bfloat162 ph, pl;
                    ph.x = h0; ph.y = h1;
                    pl.x = q0; pl.y = q1;
                    *(__nv_bfloat162*)(ch + (long)row * ldc + col) = ph;
                    *(__nv_bfloat162*)(cl + (long)row * ldc + col) = pl;
                    if (mirror) {
                        ch[(long)col * ldc + row] = h0;
                        ch[(long)(col + 1) * ldc + row] = h1;
                        cl[(long)col * ldc + row] = q0;
                        cl[(long)(col + 1) * ldc + row] = q1;
                    }
                }
            }
        }
}

// sym block map: linear 0,1,2 -> (by,bx) = (0,0),(1,0),(1,1)
DEVINL void symmap(int lin, int& by, int& bx) {
    by = (lin >= 1) ? 1 : 0;
    bx = (lin == 2) ? 1 : 0;
}

// generic wrapper.
// sym==1: grid.x = 3 lower-tri blocks, mirror off-diag. sym==0: grid (x=N tiles, y=M tiles).
// kspan>0: split-K over blockIdx.z (fp32 out, non-sym only).
__global__ __launch_bounds__(256, 2) void mm_k(
    const bf* __restrict__ Agh, const bf* __restrict__ Agl, long aStr, int lda,
    const bf* __restrict__ Bgh, const bf* __restrict__ Bgl, long bStr, int ldb, int nbValid,
    float* __restrict__ Cf, bf* __restrict__ Ch, bf* __restrict__ Cl,
    long cStr, int ldc, int nlimit, int K, int kspan, float alpha, float diag,
    int epi, int sym) {
    extern __shared__ __align__(16) char smem[];
    int z = blockIdx.z;
    const bf *Ah = Agh, *Al = Agl, *Bh = Bgh, *Bl = Bgl;
    int k0 = 0, k1 = K;
    float* cf = 0;
    bf *ch = 0, *cl = 0;
    if (kspan) {
        k0 = z * kspan;
        k1 = min(K, k0 + kspan);
        cf = Cf + (long)z * cStr;
    } else {
        Ah += (long)z * aStr; Al += (long)z * aStr;
        Bh += (long)z * bStr; Bl += (long)z * bStr;
        if (epi == 0) cf = Cf + (long)z * cStr;
        else { ch = Ch + (long)z * cStr; cl = Cl + (long)z * cStr; }
    }
    int by, bx, mirror = 0;
    if (sym) {
        symmap(blockIdx.x, by, bx);
        mirror = (by != bx);
    } else {
        by = blockIdx.y; bx = blockIdx.x;
    }
    mm_body(Ah, Al, lda, Bh, Bl, ldb, nbValid, cf, ch, cl,
            ldc, nlimit, k0, k1, alpha, diag,
            by * 128, bx * 128, epi, mirror, smem);
}

// fused Ynew + Znew (both symmetric): grid (3, 1, 2*BATCH)
__global__ __launch_bounds__(256, 2) void mmYZ_k(
    const bf* __restrict__ yh, const bf* __restrict__ yl,
    const bf* __restrict__ zyh, const bf* __restrict__ zyl, float* __restrict__ Yout,
    const bf* __restrict__ zch, const bf* __restrict__ zcl,
    bf* __restrict__ oh, bf* __restrict__ ol) {
    extern __shared__ __align__(16) char smem[];
    int z = blockIdx.z;
    int by, bx;
    symmap(blockIdx.x, by, bx);
    int mirror = (by != bx);
    if (z < BATCH) {
        long off = (long)z * 65536;
        mm_body(yh + off, yl + off, 256, zyh + off, zyl + off, 256, 256,
                Yout + off, 0, 0, 256, 256, 0, 256, 1.f, 0.f,
                by * 128, bx * 128, 0, mirror, smem);
    } else {
        long off = (long)(z - BATCH) * 65536;
        mm_body(zyh + off, zyl + off, 256, zch + off, zcl + off, 256, 256,
                0, oh + off, ol + off, 256, 256, 0, 256, 1.f, 0.f,
                by * 128, bx * 128, 1, mirror, smem);
    }
}

// ---------------- small kernels ----------------
__global__ __launch_bounds__(256) void pre_k(const float* __restrict__ pro) {
    int row = blockIdx.x;
    __shared__ float buf[HW];
    __shared__ float red[256];
    const float* p = pro + (long)row * HW;
    float s = 0.f;
    for (int i = threadIdx.x; i < HW; i += 256) { float v = p[i]; buf[i] = v; s += v; }
    red[threadIdx.x] = s;
    __syncthreads();
    for (int o = 128; o > 0; o >>= 1) {
        if (threadIdx.x < o) red[threadIdx.x] += red[threadIdx.x + o];
        __syncthreads();
    }
    float m = red[0] * (1.0f / HW);
    if (threadIdx.x == 0) g_mean[row] = m;
    long base = (long)row * KXC;
    for (int i = threadIdx.x; i < KXC; i += 256) {
        float v = (i < HW) ? buf[i] - m : 0.f;
        bf h = bhi(v);
        g_xch[base + i] = h;
        g_xcl[base + i] = blo(v, h);
    }
}

__global__ __launch_bounds__(256) void att_k(const float* __restrict__ w1,
                                             const float* __restrict__ w2,
                                             float* __restrict__ satt) {
    int b = blockIdx.x;
    __shared__ float gs[256], hs[16], av[256];
    gs[threadIdx.x] = g_mean[b * 256 + threadIdx.x];
    __syncthreads();
    if (threadIdx.x < 16) {
        float s = 0.f;
        const float* wr = w1 + threadIdx.x * 256;
        for (int c = 0; c < 256; c++) s += wr[c] * gs[c];
        hs[threadIdx.x] = s;
    }
    __syncthreads();
    float s = 0.f;
    const float* wr = w2 + threadIdx.x * 16;
#pragma unroll
    for (int c = 0; c < 16; c++) s += wr[c] * hs[c];
    float a = 1.0f / (1.0f + expf(-s));
    av[threadIdx.x] = a;
    g_attv[b * 256 + threadIdx.x] = a;
    __syncthreads();
    float* out = satt + (long)b * 65536;
    float aj = av[threadIdx.x];
    for (int i = 0; i < 256; i++) out[i * 256 + threadIdx.x] = av[i] * aj;
}

__global__ __launch_bounds__(256) void trace_k(const float* __restrict__ Aout) {
    int b = blockIdx.x, t = threadIdx.x;
    __shared__ float sm[256];
    sm[t] = Aout[(long)b * 65536 + t * 257];
    __syncthreads();
    for (int o = 128; o > 0; o >>= 1) {
        if (t < o) sm[t] += sm[t + o];
        __syncthreads();
    }
    if (t == 0) g_tr[b] = sm[0];
}

// iter0: Ypre planes; ZY0 planes; L zero.
__global__ __launch_bounds__(256) void init_k(const float* __restrict__ Aout,
                                              float e1b, float e2b2) {
    int row = blockIdx.x;
    int b = row >> 8, i = row & 255;
    int j = threadIdx.x;
    long idx = (long)row * 256 + j;
    float y = Aout[idx] / g_tr[b];
    float ai = g_attv[(b << 8) + i], aj = g_attv[(b << 8) + j];
    float j1 = (i == j) ? y * (1.0f - e1b) : y;
    float j2 = y * (1.0f - e2b2 * (1.0f - ai * aj));
    float yp = y + 0.5f * (j1 - y) + 0.5f * (j2 - y);
    float zy = ((i == j) ? 1.5f : 0.0f) - 0.5f * y;
    bf h = bhi(yp);
    g_ypreh[idx] = h;
    g_yprel[idx] = blo(yp, h);
    bf hz = bhi(zy);
    g_zy0h[idx] = hz;
    g_zy0l[idx] = blo(zy, hz);
    g_L1[idx] = 0.f;
    g_L2[idx] = 0.f;
}

// fused: reconstruct J_prev from (Yold, L), L-update, ew1(i), Y split
__global__ __launch_bounds__(256) void ewf_k(
    const float* __restrict__ Ynew, const float* __restrict__ Yold, int useTr,
    float m1p, float e1p, float d1p, float c2p,
    float e1i, float d1i, float c2i, float e3, float mui) {
    int row = blockIdx.x;
    int b = row >> 8, gi = row & 255;
    int j = threadIdx.x;
    long idx = ((long)b * 256 + gi) * 256 + j;
    float ai = g_attv[(b << 8) + gi];
    float aj = g_attv[(b << 8) + j];
    float yscale = useTr ? (1.0f / g_tr[b]) : 1.0f;
    float yn = Ynew[idx];
    float yo = Yold[idx] * yscale;
    float l1 = g_L1[idx], l2 = g_L2[idx];
    float s = 1.0f - ai * aj;
    float j1p = yo - e1p * l1;
    if (gi == j) j1p *= d1p;
    float j2p = (yo - e1p * l2) * (1.0f - c2p * s);
    float L1n = 0.9f * l1 + m1p * (j1p - yn);
    float L2n = 0.9f * l2 + m1p * (j2p - yn);
    float j1 = yn - e1i * L1n;
    if (gi == j) j1 *= d1i;
    float j2 = (yn - e1i * L2n) * (1.0f - c2i * s);
    float yp = yn + e3 * (mui * (j1 - yn) + mui * (j2 - yn) + L1n + L2n);
    g_L1[idx] = L1n;
    g_L2[idx] = L2n;
    bf h = bhi(yp);
    g_yh[idx] = h;
    g_yl[idx] = blo(yp, h);
}

__global__ __launch_bounds__(256) void feat_k(const float* __restrict__ Yfin) {
    int row = blockIdx.x;
    int b = row >> 8, r = row & 255;
    float s = sqrtf(g_tr[b]);
    long base = (long)b * TRIL + (long)r * (r + 1) / 2;
    const float* yr = Yfin + (long)row * 256;
    for (int c = threadIdx.x; c <= r; c += 256) {
        float v = yr[c] * s;
        bf h = bhi(v);
        g_feath[base + c] = h;
        g_featl[base + c] = blo(v, h);
    }
}

__global__ __launch_bounds__(256) void fcwcvt_k(const float* __restrict__ fcw) {
    long i = ((long)blockIdx.x * 256 + threadIdx.x) * 4;
    float4 v = *(const float4*)(fcw + i);
    bf h0 = bhi(v.x), h1 = bhi(v.y), h2 = bhi(v.z), h3 = bhi(v.w);
    __nv_bfloat162 a0, a1, b0, b1;
    a0.x = h0; a0.y = h1; a1.x = h2; a1.y = h3;
    b0.x = blo(v.x, h0); b0.y = blo(v.y, h1);
    b1.x = blo(v.z, h2); b1.y = blo(v.w, h3);
    *(uint2*)(g_fcwh + i) = make_uint2(*(uint32_t*)&a0, *(uint32_t*)&a1);
    *(uint2*)(g_fcwl + i) = make_uint2(*(uint32_t*)&b0, *(uint32_t*)&b1);
}

__global__ __launch_bounds__(256) void fcred_k(const float* __restrict__ fcb,
                                               float* __restrict__ cls) {
    int i = blockIdx.x * 256 + threadIdx.x;
    if (i >= BATCH * 200) return;
    int b = i / 200, o = i % 200;
    float s = fcb[o];
#pragma unroll
    for (int sp = 0; sp < FC_SPLITS; sp++)
        s += g_fcp[sp * (BATCH * 256) + b * 256 + o];
    cls[i] = s;
}

// ---------------- driver ----------------
extern "C" void kernel_launch(void* const* d_in, const int* in_sizes, int n_in,
                              void* d_out, int out_size) {
    const float* pro = (const float*)d_in[0];
    const float* w1  = (const float*)d_in[1];
    const float* w2  = (const float*)d_in[2];
    const float* fcw = (const float*)d_in[3];
    const float* fcb = (const float*)d_in[4];
    float* out = (float*)d_out;
    float* cls  = out;
    float* Aout = out + BATCH * 200;
    float* satt = Aout + MAT;

    bf *xch, *xcl, *ypreh, *yprel, *zy0h, *zy0l;
    bf *yh, *yl, *zyh, *zyl, *zah, *zal, *zbh, *zbl;
    bf *feath, *featl, *fcwh, *fcwl;
    float *Ya, *Yb, *fcp;
    cudaGetSymbolAddress((void**)&xch, g_xch);
    cudaGetSymbolAddress((void**)&xcl, g_xcl);
    cudaGetSymbolAddress((void**)&ypreh, g_ypreh);
    cudaGetSymbolAddress((void**)&yprel, g_yprel);
    cudaGetSymbolAddress((void**)&zy0h, g_zy0h);
    cudaGetSymbolAddress((void**)&zy0l, g_zy0l);
    cudaGetSymbolAddress((void**)&yh, g_yh);
    cudaGetSymbolAddress((void**)&yl, g_yl);
    cudaGetSymbolAddress((void**)&zyh, g_zyh);
    cudaGetSymbolAddress((void**)&zyl, g_zyl);
    cudaGetSymbolAddress((void**)&zah, g_zah);
    cudaGetSymbolAddress((void**)&zal, g_zal);
    cudaGetSymbolAddress((void**)&zbh, g_zbh);
    cudaGetSymbolAddress((void**)&zbl, g_zbl);
    cudaGetSymbolAddress((void**)&feath, g_feath);
    cudaGetSymbolAddress((void**)&featl, g_featl);
    cudaGetSymbolAddress((void**)&fcwh, g_fcwh);
    cudaGetSymbolAddress((void**)&fcwl, g_fcwl);
    cudaGetSymbolAddress((void**)&Ya, g_Ya);
    cudaGetSymbolAddress((void**)&Yb, g_Yb);
    cudaGetSymbolAddress((void**)&fcp, g_fcp);

    cudaFuncSetAttribute(mm_k, cudaFuncAttributeMaxDynamicSharedMemorySize, MM_SMEM);
    cudaFuncSetAttribute(mmYZ_k, cudaFuncAttributeMaxDynamicSharedMemorySize, MM_SMEM);

    pre_k<<<BATCH * DD, 256>>>(pro);                 // 0
    att_k<<<BATCH, 256>>>(w1, w2, satt);             // 1
    fcwcvt_k<<<6425, 256>>>(fcw);                    // 2

    dim3 gsym(3, 1, BATCH);
    // 3 (ncu-sampled): covariance (fp32 out, symmetric)
    mm_k<<<gsym, 256, MM_SMEM>>>(xch, xcl, (long)DD * KXC, KXC,
                          xch, xcl, (long)DD * KXC, KXC, 256,
                          Aout, nullptr, nullptr,
                          65536, 256, 256, KXC, 0, 1.0f / HW, 0.f, 0, 1);
    trace_k<<<BATCH, 256>>>(Aout);

    double mu = 0.5;
    init_k<<<BATCH * DD, 256>>>(Aout, 2e-3f, 2e-3f);
    // Y0 = Ypre @ ZY0 (symmetric) -> Ya
    mm_k<<<gsym, 256, MM_SMEM>>>(ypreh, yprel, 65536, 256,
                          zy0h, zy0l, 65536, 256, 256,
                          Ya, nullptr, nullptr,
                          65536, 256, 256, 256, 0, 1.0f, 0.f, 0, 1);
    double muPrev = mu;
    mu *= ROPH;

    float* ybuf[2] = { Ya, Yb };
    bf *zch = zy0h, *zcl = zy0l;
    dim3 gyz(3, 1, 2 * BATCH);

    for (int i = 1; i < ITERN; i++) {
        double eta = 1.0 / mu, e3 = 1.0 / (2.0 * mu);
        double etap = 1.0 / muPrev;
        float* Ynew = ybuf[(i - 1) & 1];
        const float* Yold = (i == 1) ? Aout : ybuf[i & 1];
        ewf_k<<<BATCH * DD, 256>>>(Ynew, Yold, (i == 1) ? 1 : 0,
                           (float)muPrev, (float)etap,
                           (float)(1.0 - 1e-3 * etap), (float)(1e-3 * etap),
                           (float)eta, (float)(1.0 - 1e-3 * eta), (float)(1e-3 * eta),
                           (float)e3, (float)mu);
        // ZY = 1.5I - 0.5 * Z @ Y (symmetric)
        mm_k<<<gsym, 256, MM_SMEM>>>(zch, zcl, 65536, 256,
                              yh, yl, 65536, 256, 256,
                              nullptr, zyh, zyl,
                              65536, 256, 256, 256, 0, -0.5f, 1.5f, 1, 1);
        if (i != ITERN - 1) {
            bf* oh = (i & 1) ? zah : zbh;
            bf* ol = (i & 1) ? zal : zbl;
            // fused: Ynew = Y @ ZY (fp32) AND Znew = ZY @ Z (planes), both symmetric
            mmYZ_k<<<gyz, 256, MM_SMEM>>>(yh, yl, zyh, zyl, ybuf[i & 1],
                                          zch, zcl, oh, ol);
            zch = oh; zcl = ol;
        } else {
            mm_k<<<gsym, 256, MM_SMEM>>>(yh, yl, 65536, 256,
                                  zyh, zyl, 65536, 256, 256,
                                  ybuf[i & 1], nullptr, nullptr,
                                  65536, 256, 256, 256, 0, 1.0f, 0.f, 0, 1);
        }
        if (i < ITERN - 1) {
            muPrev = mu;
            mu *= ROPH;
        }
    }

    feat_k<<<BATCH * DD, 256>>>(ybuf[(ITERN - 1) & 1]);
    dim3 gfc(2, 1, FC_SPLITS);
    mm_k<<<gfc, 256, MM_SMEM>>>(feath, featl, 0, TRIL,
                          fcwh, fcwl, 0, TRIL, 200,
                          fcp, nullptr, nullptr,
                          (long)BATCH * 256, 256, 200, TRIL, FC_KSPAN, 1.0f, 0.f, 0, 0);
    fcred_k<<<100, 256>>>(fcb, cls);
}